// round 10
// baseline (speedup 1.0000x reference)
#include <cuda_runtime.h>
#include <cuda_bf16.h>
#include <cuda_fp16.h>
#include <cstdint>

// Problem constants (GCL_GCN: N=50000, E=800000, FEAT=128, HID1=128, HID2=64)
#define N_MAX   50000
#define E_MAX   800000
#define HID1    128
#define HID2    64
#define ELL_W   128     // max neighbors stored per node (deg~Poisson(16); P(>=128)~0)

// ---------------- scratch (static device globals; no allocation) -------------
__device__ __half g_h1 [(size_t)N_MAX * HID1];   // X @ W1 (fp16 payload)
__device__ float  g_a1 [(size_t)N_MAX * HID1];   // relu(aggregated layer1), fp32
__device__ __half g_h2 [(size_t)N_MAX * HID2];   // a1 @ W2 (fp16 payload)
__device__ int    g_cnt[N_MAX];                  // in-degree (excl self-loop)
__device__ int    g_ell[(size_t)N_MAX * ELL_W];  // ELL adjacency: src ids per dst

// ---------------- helpers -----------------------------------------------------
__device__ __forceinline__ uint32_t cvt_tf32(float f) {
    uint32_t r;
    asm("cvt.rna.tf32.f32 %0, %1;" : "=r"(r) : "f"(f));
    return r;
}
__device__ __forceinline__ void mma_tf32(
    float* c, const uint32_t* a, uint32_t b0, uint32_t b1)
{
    asm volatile(
        "mma.sync.aligned.m16n8k8.row.col.f32.tf32.tf32.f32 "
        "{%0,%1,%2,%3}, {%4,%5,%6,%7}, {%8,%9}, {%0,%1,%2,%3};"
        : "+f"(c[0]), "+f"(c[1]), "+f"(c[2]), "+f"(c[3])
        : "r"(a[0]), "r"(a[1]), "r"(a[2]), "r"(a[3]), "r"(b0), "r"(b1));
}
__device__ __forceinline__ float4 half4_to_float4(uint2 u) {
    float2 lo = __half22float2(*reinterpret_cast<__half2*>(&u.x));
    float2 hi = __half22float2(*reinterpret_cast<__half2*>(&u.y));
    return make_float4(lo.x, lo.y, hi.x, hi.y);
}
__device__ __forceinline__ float dinv_of(int deg) {
    return rsqrtf((float)(deg + 1));            // +1 self-loop
}

// ---------------- ELL build: one pass, 4 edges/thread ---------------------------
__global__ void fill_ell_kernel(
    const int* __restrict__ src, const int* __restrict__ dst,
    int* __restrict__ cnt, int* __restrict__ ell, int E)
{
    int base = (blockIdx.x * blockDim.x + threadIdx.x) * 4;
    if (base + 3 < E) {
        int d0 = dst[base],     d1 = dst[base + 1];
        int d2 = dst[base + 2], d3 = dst[base + 3];
        int s0 = src[base],     s1 = src[base + 1];
        int s2 = src[base + 2], s3 = src[base + 3];
        int p0 = atomicAdd(&cnt[d0], 1);
        int p1 = atomicAdd(&cnt[d1], 1);
        int p2 = atomicAdd(&cnt[d2], 1);
        int p3 = atomicAdd(&cnt[d3], 1);
        if (p0 < ELL_W) ell[(size_t)d0 * ELL_W + p0] = s0;
        if (p1 < ELL_W) ell[(size_t)d1 * ELL_W + p1] = s1;
        if (p2 < ELL_W) ell[(size_t)d2 * ELL_W + p2] = s2;
        if (p3 < ELL_W) ell[(size_t)d3 * ELL_W + p3] = s3;
    } else {
        for (int e = base; e < E; ++e) {
            int pos = atomicAdd(&cnt[dst[e]], 1);
            if (pos < ELL_W) ell[(size_t)dst[e] * ELL_W + pos] = src[e];
        }
    }
}

// ---------------- tf32 HMMA GEMM: H(fp16) = X[N,128] @ W[128,COUT] -------------
// CTA: 256 thr (8 warps), tile 128 rows x COUT cols. Warp tile 32 x COUT/2.
// mma.sync m16n8k8 tf32. Padded SMEM strides keep all frag LDS conflict-free.
#define HG_SMEM(COUT) ((128 * 132 + 128 * ((COUT) + 4)) * 4)

template<int COUT>
__global__ __launch_bounds__(256) void hmma_gemm_kernel(
    const float* __restrict__ X, const float* __restrict__ W,
    __half* __restrict__ H, int N)
{
    constexpr int XS = 132;
    constexpr int WS = COUT + 4;
    constexpr int NT = COUT / 16;
    extern __shared__ uint32_t smu[];
    uint32_t* Xs = smu;
    uint32_t* Ws = smu + 128 * XS;

    const int tid   = threadIdx.x;
    const int wid   = tid >> 5;
    const int lane  = tid & 31;
    const int g     = lane >> 2;
    const int t     = lane & 3;
    const int rbase = blockIdx.x * 128;

    const float4* Xg4 = reinterpret_cast<const float4*>(X);
    #pragma unroll
    for (int it = 0; it < 16; ++it) {
        int i  = tid + it * 256;
        int r  = i >> 5, k4 = i & 31;
        int gr = rbase + r;
        float4 v = (gr < N) ? Xg4[(size_t)gr * 32 + k4]
                            : make_float4(0.f, 0.f, 0.f, 0.f);
        uint4 u = make_uint4(cvt_tf32(v.x), cvt_tf32(v.y),
                             cvt_tf32(v.z), cvt_tf32(v.w));
        *reinterpret_cast<uint4*>(&Xs[r * XS + k4 * 4]) = u;
    }
    const float4* Wg4 = reinterpret_cast<const float4*>(W);
    constexpr int W4 = COUT / 4;
    #pragma unroll
    for (int it = 0; it < (128 * W4) / 256; ++it) {
        int i = tid + it * 256;
        int k = i / W4, n4 = i % W4;
        float4 v = Wg4[i];
        uint4 u = make_uint4(cvt_tf32(v.x), cvt_tf32(v.y),
                             cvt_tf32(v.z), cvt_tf32(v.w));
        *reinterpret_cast<uint4*>(&Ws[k * WS + n4 * 4]) = u;
    }
    __syncthreads();

    const int wr = (wid >> 1) * 32;
    const int wc = (wid & 1) * (COUT / 2);
    float c[2][NT][4];
    #pragma unroll
    for (int rb = 0; rb < 2; ++rb)
        #pragma unroll
        for (int nt = 0; nt < NT; ++nt)
            #pragma unroll
            for (int j = 0; j < 4; ++j) c[rb][nt][j] = 0.f;

    #pragma unroll
    for (int ks = 0; ks < 16; ++ks) {
        const int k0 = ks * 8;
        uint32_t a[2][4];
        #pragma unroll
        for (int rb = 0; rb < 2; ++rb) {
            const uint32_t* xb = &Xs[(wr + rb * 16 + g) * XS + k0 + t];
            a[rb][0] = xb[0];
            a[rb][2] = xb[4];
            a[rb][1] = xb[8 * XS];
            a[rb][3] = xb[8 * XS + 4];
        }
        #pragma unroll
        for (int nt = 0; nt < NT; ++nt) {
            uint32_t b0 = Ws[(k0 + t) * WS + wc + nt * 8 + g];
            uint32_t b1 = Ws[(k0 + t + 4) * WS + wc + nt * 8 + g];
            mma_tf32(c[0][nt], a[0], b0, b1);
            mma_tf32(c[1][nt], a[1], b0, b1);
        }
    }

    #pragma unroll
    for (int rb = 0; rb < 2; ++rb) {
        int r0 = rbase + wr + rb * 16 + g;
        #pragma unroll
        for (int nt = 0; nt < NT; ++nt) {
            int col = wc + nt * 8 + 2 * t;
            if (r0 < N)
                *reinterpret_cast<__half2*>(&H[(size_t)r0 * COUT + col]) =
                    __floats2half2_rn(c[rb][nt][0], c[rb][nt][1]);
            if (r0 + 8 < N)
                *reinterpret_cast<__half2*>(&H[(size_t)(r0 + 8) * COUT + col]) =
                    __floats2half2_rn(c[rb][nt][2], c[rb][nt][3]);
        }
    }
}

// ---------------- ELL gather, 128 feats fp16 in / fp32 out, unroll-4 -----------
// out = relu(dd * (dd*h[d] + sum_s dinv_s*h[s]) + b),  dd = rsqrt(cnt[d]+1)
__global__ __launch_bounds__(256) void gather128_kernel(
    const __half* __restrict__ hs, const int* __restrict__ cnt,
    const int* __restrict__ ell, const float* __restrict__ b,
    float* __restrict__ out, int N)
{
    int node = (blockIdx.x * blockDim.x + threadIdx.x) >> 5;
    int lane = threadIdx.x & 31;
    if (node >= N) return;
    int cn   = cnt[node];
    int cmax = cn < ELL_W ? cn : ELL_W;
    float dd = dinv_of(cn);
    const uint2* h8   = reinterpret_cast<const uint2*>(hs);
    const int4*  row4 = reinterpret_cast<const int4*>(ell + (size_t)node * ELL_W);

    float4 sv = half4_to_float4(h8[(size_t)node * 32 + lane]);
    float4 a0 = make_float4(sv.x * dd, sv.y * dd, sv.z * dd, sv.w * dd);
    float4 a1 = make_float4(0.f, 0.f, 0.f, 0.f);
    float4 a2 = make_float4(0.f, 0.f, 0.f, 0.f);
    float4 a3 = make_float4(0.f, 0.f, 0.f, 0.f);

    int j = 0;
    for (; j + 3 < cmax; j += 4) {
        int4 ss = row4[j >> 2];                  // broadcast, 16B aligned
        float n0 = dinv_of(cnt[ss.x]);
        float n1 = dinv_of(cnt[ss.y]);
        float n2 = dinv_of(cnt[ss.z]);
        float n3 = dinv_of(cnt[ss.w]);
        float4 v0 = half4_to_float4(h8[(size_t)ss.x * 32 + lane]);
        float4 v1 = half4_to_float4(h8[(size_t)ss.y * 32 + lane]);
        float4 v2 = half4_to_float4(h8[(size_t)ss.z * 32 + lane]);
        float4 v3 = half4_to_float4(h8[(size_t)ss.w * 32 + lane]);
        a0.x = fmaf(v0.x, n0, a0.x); a0.y = fmaf(v0.y, n0, a0.y);
        a0.z = fmaf(v0.z, n0, a0.z); a0.w = fmaf(v0.w, n0, a0.w);
        a1.x = fmaf(v1.x, n1, a1.x); a1.y = fmaf(v1.y, n1, a1.y);
        a1.z = fmaf(v1.z, n1, a1.z); a1.w = fmaf(v1.w, n1, a1.w);
        a2.x = fmaf(v2.x, n2, a2.x); a2.y = fmaf(v2.y, n2, a2.y);
        a2.z = fmaf(v2.z, n2, a2.z); a2.w = fmaf(v2.w, n2, a2.w);
        a3.x = fmaf(v3.x, n3, a3.x); a3.y = fmaf(v3.y, n3, a3.y);
        a3.z = fmaf(v3.z, n3, a3.z); a3.w = fmaf(v3.w, n3, a3.w);
    }
    const int* row = ell + (size_t)node * ELL_W;
    for (; j < cmax; ++j) {
        int s = row[j];
        float n0 = dinv_of(cnt[s]);
        float4 v0 = half4_to_float4(h8[(size_t)s * 32 + lane]);
        a0.x = fmaf(v0.x, n0, a0.x); a0.y = fmaf(v0.y, n0, a0.y);
        a0.z = fmaf(v0.z, n0, a0.z); a0.w = fmaf(v0.w, n0, a0.w);
    }
    float4 bv = reinterpret_cast<const float4*>(b)[lane];
    float4 r;
    r.x = fmaxf(fmaf(dd, (a0.x + a1.x) + (a2.x + a3.x), bv.x), 0.f);
    r.y = fmaxf(fmaf(dd, (a0.y + a1.y) + (a2.y + a3.y), bv.y), 0.f);
    r.z = fmaxf(fmaf(dd, (a0.z + a1.z) + (a2.z + a3.z), bv.z), 0.f);
    r.w = fmaxf(fmaf(dd, (a0.w + a1.w) + (a2.w + a3.w), bv.w), 0.f);
    reinterpret_cast<float4*>(out)[(size_t)node * 32 + lane] = r;
}

// ---------------- ELL gather, 64 feats fp16 in / fp32 out, unroll-4 ------------
__global__ __launch_bounds__(256) void gather64_kernel(
    const __half* __restrict__ hs, const int* __restrict__ cnt,
    const int* __restrict__ ell, const float* __restrict__ b,
    float* __restrict__ out, int N)
{
    int node = (blockIdx.x * blockDim.x + threadIdx.x) >> 5;
    int lane = threadIdx.x & 31;
    if (node >= N) return;
    int cn   = cnt[node];
    int cmax = cn < ELL_W ? cn : ELL_W;
    float dd = dinv_of(cn);
    const __half2* h2p  = reinterpret_cast<const __half2*>(hs);
    const int4*    row4 = reinterpret_cast<const int4*>(ell + (size_t)node * ELL_W);

    float2 sv = __half22float2(h2p[(size_t)node * 32 + lane]);
    float2 a0 = make_float2(sv.x * dd, sv.y * dd);
    float2 a1 = make_float2(0.f, 0.f);
    float2 a2 = make_float2(0.f, 0.f);
    float2 a3 = make_float2(0.f, 0.f);

    int j = 0;
    for (; j + 3 < cmax; j += 4) {
        int4 ss = row4[j >> 2];
        float n0 = dinv_of(cnt[ss.x]);
        float n1 = dinv_of(cnt[ss.y]);
        float n2 = dinv_of(cnt[ss.z]);
        float n3 = dinv_of(cnt[ss.w]);
        float2 v0 = __half22float2(h2p[(size_t)ss.x * 32 + lane]);
        float2 v1 = __half22float2(h2p[(size_t)ss.y * 32 + lane]);
        float2 v2 = __half22float2(h2p[(size_t)ss.z * 32 + lane]);
        float2 v3 = __half22float2(h2p[(size_t)ss.w * 32 + lane]);
        a0.x = fmaf(v0.x, n0, a0.x); a0.y = fmaf(v0.y, n0, a0.y);
        a1.x = fmaf(v1.x, n1, a1.x); a1.y = fmaf(v1.y, n1, a1.y);
        a2.x = fmaf(v2.x, n2, a2.x); a2.y = fmaf(v2.y, n2, a2.y);
        a3.x = fmaf(v3.x, n3, a3.x); a3.y = fmaf(v3.y, n3, a3.y);
    }
    const int* row = ell + (size_t)node * ELL_W;
    for (; j < cmax; ++j) {
        int s = row[j];
        float n0 = dinv_of(cnt[s]);
        float2 v0 = __half22float2(h2p[(size_t)s * 32 + lane]);
        a0.x = fmaf(v0.x, n0, a0.x); a0.y = fmaf(v0.y, n0, a0.y);
    }
    float2 bv = reinterpret_cast<const float2*>(b)[lane];
    float2 r;
    r.x = fmaf(dd, (a0.x + a1.x) + (a2.x + a3.x), bv.x);
    r.y = fmaf(dd, (a0.y + a1.y) + (a2.y + a3.y), bv.y);
    reinterpret_cast<float2*>(out)[(size_t)node * 32 + lane] = r;
}

// -----------------------------------------------------------------------------
extern "C" void kernel_launch(void* const* d_in, const int* in_sizes, int n_in,
                              void* d_out, int out_size)
{
    const float* x  = (const float*)d_in[0];
    const int*   ei = (const int*)  d_in[1];
    const float* W1 = (const float*)d_in[2];
    const float* b1 = (const float*)d_in[3];
    const float* W2 = (const float*)d_in[4];
    const float* b2 = (const float*)d_in[5];
    float* out = (float*)d_out;

    const int hid1 = in_sizes[3];            // 128
    const int feat = in_sizes[2] / hid1;     // 128
    const int N    = in_sizes[0] / feat;     // 50000
    const int E    = in_sizes[1] / 2;        // 800000
    const int* src = ei;
    const int* dst = ei + E;

    void *p_h1, *p_a1, *p_h2, *p_cnt, *p_ell;
    cudaGetSymbolAddress(&p_h1,  g_h1);
    cudaGetSymbolAddress(&p_a1,  g_a1);
    cudaGetSymbolAddress(&p_h2,  g_h2);
    cudaGetSymbolAddress(&p_cnt, g_cnt);
    cudaGetSymbolAddress(&p_ell, g_ell);
    __half* h1  = (__half*)p_h1;
    float*  a1  = (float*) p_a1;
    __half* h2  = (__half*)p_h2;
    int*    cnt = (int*)   p_cnt;
    int*    ell = (int*)   p_ell;

    static cudaStream_t s_csr = nullptr;
    static cudaEvent_t  ev_root = nullptr, ev_csr = nullptr;
    if (s_csr == nullptr) {
        cudaFuncSetAttribute(hmma_gemm_kernel<HID1>,
                             cudaFuncAttributeMaxDynamicSharedMemorySize, HG_SMEM(HID1));
        cudaFuncSetAttribute(hmma_gemm_kernel<HID2>,
                             cudaFuncAttributeMaxDynamicSharedMemorySize, HG_SMEM(HID2));
        cudaStreamCreateWithFlags(&s_csr, cudaStreamNonBlocking);
        cudaEventCreateWithFlags(&ev_root, cudaEventDisableTiming);
        cudaEventCreateWithFlags(&ev_csr,  cudaEventDisableTiming);
    }

    const int T = 256;
    const int gx    = (N + 127) / 128;
    const int gwarp = (N * 32 + T - 1) / T;
    const int e4    = (E + 3) / 4;                  // ILP-4 edge threads

    // ---- fork: ELL build on side stream, GEMM1 on main stream ----
    cudaEventRecord(ev_root, 0);
    cudaStreamWaitEvent(s_csr, ev_root, 0);

    cudaMemsetAsync(cnt, 0, (size_t)N * sizeof(int), s_csr);
    fill_ell_kernel<<<(e4 + T - 1) / T, T, 0, s_csr>>>(src, dst, cnt, ell, E);
    cudaEventRecord(ev_csr, s_csr);

    // layer 1 GEMM (independent of graph build): h1 = x @ W1 (fp16 out)
    hmma_gemm_kernel<HID1><<<gx, 256, HG_SMEM(HID1)>>>(x, W1, h1, N);

    // join: gathers need ELL + cnt
    cudaStreamWaitEvent(0, ev_csr, 0);

    // gather layer 1: a1 = relu(dd*(dd*h1[d] + sum dinv_s*h1[s]) + b1)
    gather128_kernel<<<gwarp, T>>>(h1, cnt, ell, b1, a1, N);

    // layer 2 GEMM: h2 = a1 @ W2 (fp16 out)
    hmma_gemm_kernel<HID2><<<gx, 256, HG_SMEM(HID2)>>>(a1, W2, h2, N);

    // gather layer 2 into out (no relu, fp32 out)
    gather64_kernel<<<gwarp, T>>>(h2, cnt, ell, b2, out, N);
}

// round 11
// speedup vs baseline: 1.0135x; 1.0135x over previous
#include <cuda_runtime.h>
#include <cuda_bf16.h>
#include <cuda_fp16.h>
#include <cstdint>

// Problem constants (GCL_GCN: N=50000, E=800000, FEAT=128, HID1=128, HID2=64)
#define N_MAX   50000
#define E_MAX   800000
#define HID1    128
#define HID2    64
#define SCAN_B  1024
#define SCAN_NBLOCKS ((N_MAX + SCAN_B - 1) / SCAN_B + 1)

// ---------------- scratch (static device globals; no allocation) -------------
__device__ __half g_h1 [(size_t)N_MAX * HID1];   // X @ W1 (fp16 payload)
__device__ float  g_a1 [(size_t)N_MAX * HID1];   // relu(aggregated layer1), fp32
__device__ __half g_h2 [(size_t)N_MAX * HID2];   // a1 @ W2 (fp16 payload)
__device__ int    g_deg [N_MAX];
__device__ float  g_dinv[N_MAX];
__device__ int    g_rowstart[N_MAX + 1];
__device__ int    g_cursor  [N_MAX];
__device__ int    g_csrc    [E_MAX];             // edges sorted by dst -> src ids
__device__ int    g_bsum    [SCAN_NBLOCKS + 1];  // per-block scan sums

// ---------------- helpers -----------------------------------------------------
__device__ __forceinline__ uint32_t cvt_tf32(float f) {
    uint32_t r;
    asm("cvt.rna.tf32.f32 %0, %1;" : "=r"(r) : "f"(f));
    return r;
}
__device__ __forceinline__ void mma_tf32(
    float* c, const uint32_t* a, uint32_t b0, uint32_t b1)
{
    asm volatile(
        "mma.sync.aligned.m16n8k8.row.col.f32.tf32.tf32.f32 "
        "{%0,%1,%2,%3}, {%4,%5,%6,%7}, {%8,%9}, {%0,%1,%2,%3};"
        : "+f"(c[0]), "+f"(c[1]), "+f"(c[2]), "+f"(c[3])
        : "r"(a[0]), "r"(a[1]), "r"(a[2]), "r"(a[3]), "r"(b0), "r"(b1));
}
__device__ __forceinline__ float4 half4_to_float4(uint2 u) {
    float2 lo = __half22float2(*reinterpret_cast<__half2*>(&u.x));
    float2 hi = __half22float2(*reinterpret_cast<__half2*>(&u.y));
    return make_float4(lo.x, lo.y, hi.x, hi.y);
}

// ---------------- degree count (4 edges/thread for atomic MLP) -----------------
__global__ void count_deg_kernel(const int* __restrict__ dst, int* __restrict__ deg, int E) {
    int base = (blockIdx.x * blockDim.x + threadIdx.x) * 4;
    if (base + 3 < E) {
        int d0 = dst[base], d1 = dst[base + 1], d2 = dst[base + 2], d3 = dst[base + 3];
        atomicAdd(&deg[d0], 1);
        atomicAdd(&deg[d1], 1);
        atomicAdd(&deg[d2], 1);
        atomicAdd(&deg[d3], 1);
    } else {
        for (int e = base; e < E; ++e) atomicAdd(&deg[dst[e]], 1);
    }
}

// ---------------- scan phase A: per-block excl scan + dinv ---------------------
__global__ __launch_bounds__(SCAN_B) void scan_blocks_kernel(
    const int* __restrict__ deg, int* __restrict__ row_start,
    int* __restrict__ bsum, float* __restrict__ dinv, int N)
{
    __shared__ int warp_sums[32];
    const int lane = threadIdx.x & 31;
    const int wid  = threadIdx.x >> 5;
    int i = blockIdx.x * SCAN_B + threadIdx.x;
    int v = (i < N) ? deg[i] : 0;
    if (i < N) dinv[i] = rsqrtf((float)(v + 1));   // +1 self-loop
    int x = v;
    #pragma unroll
    for (int o = 1; o < 32; o <<= 1) {
        int t = __shfl_up_sync(0xffffffffu, x, o);
        if (lane >= o) x += t;
    }
    if (lane == 31) warp_sums[wid] = x;
    __syncthreads();
    if (wid == 0) {
        int ws = warp_sums[lane];
        #pragma unroll
        for (int o = 1; o < 32; o <<= 1) {
            int t = __shfl_up_sync(0xffffffffu, ws, o);
            if (lane >= o) ws += t;
        }
        warp_sums[lane] = ws;
    }
    __syncthreads();
    int excl = x - v + (wid > 0 ? warp_sums[wid - 1] : 0);
    if (i < N) row_start[i] = excl;
    if (threadIdx.x == SCAN_B - 1) bsum[blockIdx.x] = excl + v;
}

// ---------------- scan phase B: add block offsets (masked reduce per block) ----
__global__ __launch_bounds__(SCAN_B) void scan_add_kernel(
    int* __restrict__ row_start, int* __restrict__ cursor,
    const int* __restrict__ bsum, int N, int nscan, int E)
{
    __shared__ int s_off;
    if (threadIdx.x < 32) {
        int lane = threadIdx.x;
        int v = 0;
        if (lane < nscan && lane < blockIdx.x) v = bsum[lane];
        if (lane + 32 < nscan && lane + 32 < (int)blockIdx.x) v += bsum[lane + 32];
        #pragma unroll
        for (int o = 16; o; o >>= 1) v += __shfl_xor_sync(0xffffffffu, v, o);
        if (lane == 0) s_off = v;
    }
    __syncthreads();
    int i = blockIdx.x * SCAN_B + threadIdx.x;
    if (i < N) {
        int r = row_start[i] + s_off;
        row_start[i] = r;
        cursor[i]    = r;
    }
    if (i == 0) row_start[N] = E;    // total edge count is known
}

// ---------------- fill CSR (4 edges/thread for atomic MLP) ---------------------
__global__ void fill_csr_kernel(
    const int* __restrict__ src, const int* __restrict__ dst,
    int* __restrict__ cursor, int* __restrict__ csrc, int E)
{
    int base = (blockIdx.x * blockDim.x + threadIdx.x) * 4;
    if (base + 3 < E) {
        int d0 = dst[base],     d1 = dst[base + 1];
        int d2 = dst[base + 2], d3 = dst[base + 3];
        int s0 = src[base],     s1 = src[base + 1];
        int s2 = src[base + 2], s3 = src[base + 3];
        int p0 = atomicAdd(&cursor[d0], 1);
        int p1 = atomicAdd(&cursor[d1], 1);
        int p2 = atomicAdd(&cursor[d2], 1);
        int p3 = atomicAdd(&cursor[d3], 1);
        csrc[p0] = s0; csrc[p1] = s1; csrc[p2] = s2; csrc[p3] = s3;
    } else {
        for (int e = base; e < E; ++e) {
            int pos = atomicAdd(&cursor[dst[e]], 1);
            csrc[pos] = src[e];
        }
    }
}

// ---------------- tf32 HMMA GEMM: H(fp16) = X[N,128] @ W[128,COUT] -------------
// CTA: 256 thr (8 warps), tile 128 rows x COUT cols. Warp tile 32 x COUT/2.
// mma.sync m16n8k8 tf32. Padded SMEM strides keep all frag LDS conflict-free.
#define HG_SMEM(COUT) ((128 * 132 + 128 * ((COUT) + 4)) * 4)

template<int COUT>
__global__ __launch_bounds__(256) void hmma_gemm_kernel(
    const float* __restrict__ X, const float* __restrict__ W,
    __half* __restrict__ H, int N)
{
    constexpr int XS = 132;
    constexpr int WS = COUT + 4;
    constexpr int NT = COUT / 16;
    extern __shared__ uint32_t smu[];
    uint32_t* Xs = smu;
    uint32_t* Ws = smu + 128 * XS;

    const int tid   = threadIdx.x;
    const int wid   = tid >> 5;
    const int lane  = tid & 31;
    const int g     = lane >> 2;
    const int t     = lane & 3;
    const int rbase = blockIdx.x * 128;

    const float4* Xg4 = reinterpret_cast<const float4*>(X);
    #pragma unroll
    for (int it = 0; it < 16; ++it) {
        int i  = tid + it * 256;
        int r  = i >> 5, k4 = i & 31;
        int gr = rbase + r;
        float4 v = (gr < N) ? Xg4[(size_t)gr * 32 + k4]
                            : make_float4(0.f, 0.f, 0.f, 0.f);
        uint4 u = make_uint4(cvt_tf32(v.x), cvt_tf32(v.y),
                             cvt_tf32(v.z), cvt_tf32(v.w));
        *reinterpret_cast<uint4*>(&Xs[r * XS + k4 * 4]) = u;
    }
    const float4* Wg4 = reinterpret_cast<const float4*>(W);
    constexpr int W4 = COUT / 4;
    #pragma unroll
    for (int it = 0; it < (128 * W4) / 256; ++it) {
        int i = tid + it * 256;
        int k = i / W4, n4 = i % W4;
        float4 v = Wg4[i];
        uint4 u = make_uint4(cvt_tf32(v.x), cvt_tf32(v.y),
                             cvt_tf32(v.z), cvt_tf32(v.w));
        *reinterpret_cast<uint4*>(&Ws[k * WS + n4 * 4]) = u;
    }
    __syncthreads();

    const int wr = (wid >> 1) * 32;
    const int wc = (wid & 1) * (COUT / 2);
    float c[2][NT][4];
    #pragma unroll
    for (int rb = 0; rb < 2; ++rb)
        #pragma unroll
        for (int nt = 0; nt < NT; ++nt)
            #pragma unroll
            for (int j = 0; j < 4; ++j) c[rb][nt][j] = 0.f;

    #pragma unroll
    for (int ks = 0; ks < 16; ++ks) {
        const int k0 = ks * 8;
        uint32_t a[2][4];
        #pragma unroll
        for (int rb = 0; rb < 2; ++rb) {
            const uint32_t* xb = &Xs[(wr + rb * 16 + g) * XS + k0 + t];
            a[rb][0] = xb[0];
            a[rb][2] = xb[4];
            a[rb][1] = xb[8 * XS];
            a[rb][3] = xb[8 * XS + 4];
        }
        #pragma unroll
        for (int nt = 0; nt < NT; ++nt) {
            uint32_t b0 = Ws[(k0 + t) * WS + wc + nt * 8 + g];
            uint32_t b1 = Ws[(k0 + t + 4) * WS + wc + nt * 8 + g];
            mma_tf32(c[0][nt], a[0], b0, b1);
            mma_tf32(c[1][nt], a[1], b0, b1);
        }
    }

    #pragma unroll
    for (int rb = 0; rb < 2; ++rb) {
        int r0 = rbase + wr + rb * 16 + g;
        #pragma unroll
        for (int nt = 0; nt < NT; ++nt) {
            int col = wc + nt * 8 + 2 * t;
            if (r0 < N)
                *reinterpret_cast<__half2*>(&H[(size_t)r0 * COUT + col]) =
                    __floats2half2_rn(c[rb][nt][0], c[rb][nt][1]);
            if (r0 + 8 < N)
                *reinterpret_cast<__half2*>(&H[(size_t)(r0 + 8) * COUT + col]) =
                    __floats2half2_rn(c[rb][nt][2], c[rb][nt][3]);
        }
    }
}

// ---------------- CSR gather, 128 feats fp16 in / fp32 out, unroll-4 -----------
// sum = dinv_d * h[d] + sum_s dinv_s * h[s];  out = relu(dinv_d * sum + b)
__global__ __launch_bounds__(256) void gather128_kernel(
    const __half* __restrict__ hs, const int* __restrict__ rs,
    const int* __restrict__ csrc, const float* __restrict__ dinv,
    const float* __restrict__ b, float* __restrict__ out, int N)
{
    int node = (blockIdx.x * blockDim.x + threadIdx.x) >> 5;
    int lane = threadIdx.x & 31;
    if (node >= N) return;
    int beg = rs[node], end = rs[node + 1];
    const uint2* h8 = reinterpret_cast<const uint2*>(hs);  // 4 halves per lane
    float dd = dinv[node];

    float4 sv = half4_to_float4(h8[(size_t)node * 32 + lane]);
    float4 a0 = make_float4(sv.x * dd, sv.y * dd, sv.z * dd, sv.w * dd);
    float4 a1 = make_float4(0.f, 0.f, 0.f, 0.f);
    float4 a2 = make_float4(0.f, 0.f, 0.f, 0.f);
    float4 a3 = make_float4(0.f, 0.f, 0.f, 0.f);
    int j = beg;
    for (; j + 3 < end; j += 4) {
        int s0 = csrc[j],     s1 = csrc[j + 1];
        int s2 = csrc[j + 2], s3 = csrc[j + 3];
        float n0 = dinv[s0], n1 = dinv[s1], n2 = dinv[s2], n3 = dinv[s3];
        float4 v0 = half4_to_float4(h8[(size_t)s0 * 32 + lane]);
        float4 v1 = half4_to_float4(h8[(size_t)s1 * 32 + lane]);
        float4 v2 = half4_to_float4(h8[(size_t)s2 * 32 + lane]);
        float4 v3 = half4_to_float4(h8[(size_t)s3 * 32 + lane]);
        a0.x = fmaf(v0.x, n0, a0.x); a0.y = fmaf(v0.y, n0, a0.y);
        a0.z = fmaf(v0.z, n0, a0.z); a0.w = fmaf(v0.w, n0, a0.w);
        a1.x = fmaf(v1.x, n1, a1.x); a1.y = fmaf(v1.y, n1, a1.y);
        a1.z = fmaf(v1.z, n1, a1.z); a1.w = fmaf(v1.w, n1, a1.w);
        a2.x = fmaf(v2.x, n2, a2.x); a2.y = fmaf(v2.y, n2, a2.y);
        a2.z = fmaf(v2.z, n2, a2.z); a2.w = fmaf(v2.w, n2, a2.w);
        a3.x = fmaf(v3.x, n3, a3.x); a3.y = fmaf(v3.y, n3, a3.y);
        a3.z = fmaf(v3.z, n3, a3.z); a3.w = fmaf(v3.w, n3, a3.w);
    }
    for (; j < end; ++j) {
        int s0 = csrc[j];
        float n0 = dinv[s0];
        float4 v0 = half4_to_float4(h8[(size_t)s0 * 32 + lane]);
        a0.x = fmaf(v0.x, n0, a0.x); a0.y = fmaf(v0.y, n0, a0.y);
        a0.z = fmaf(v0.z, n0, a0.z); a0.w = fmaf(v0.w, n0, a0.w);
    }
    float4 bv = reinterpret_cast<const float4*>(b)[lane];
    float4 r;
    r.x = fmaxf(fmaf(dd, (a0.x + a1.x) + (a2.x + a3.x), bv.x), 0.f);
    r.y = fmaxf(fmaf(dd, (a0.y + a1.y) + (a2.y + a3.y), bv.y), 0.f);
    r.z = fmaxf(fmaf(dd, (a0.z + a1.z) + (a2.z + a3.z), bv.z), 0.f);
    r.w = fmaxf(fmaf(dd, (a0.w + a1.w) + (a2.w + a3.w), bv.w), 0.f);
    reinterpret_cast<float4*>(out)[(size_t)node * 32 + lane] = r;
}

// ---------------- CSR gather, 64 feats fp16 in / fp32 out, unroll-4 ------------
__global__ __launch_bounds__(256) void gather64_kernel(
    const __half* __restrict__ hs, const int* __restrict__ rs,
    const int* __restrict__ csrc, const float* __restrict__ dinv,
    const float* __restrict__ b, float* __restrict__ out, int N)
{
    int node = (blockIdx.x * blockDim.x + threadIdx.x) >> 5;
    int lane = threadIdx.x & 31;
    if (node >= N) return;
    int beg = rs[node], end = rs[node + 1];
    const __half2* h2p = reinterpret_cast<const __half2*>(hs);  // 2 halves per lane
    float dd = dinv[node];

    float2 sv = __half22float2(h2p[(size_t)node * 32 + lane]);
    float2 a0 = make_float2(sv.x * dd, sv.y * dd);
    float2 a1 = make_float2(0.f, 0.f);
    float2 a2 = make_float2(0.f, 0.f);
    float2 a3 = make_float2(0.f, 0.f);
    int j = beg;
    for (; j + 3 < end; j += 4) {
        int s0 = csrc[j],     s1 = csrc[j + 1];
        int s2 = csrc[j + 2], s3 = csrc[j + 3];
        float n0 = dinv[s0], n1 = dinv[s1], n2 = dinv[s2], n3 = dinv[s3];
        float2 v0 = __half22float2(h2p[(size_t)s0 * 32 + lane]);
        float2 v1 = __half22float2(h2p[(size_t)s1 * 32 + lane]);
        float2 v2 = __half22float2(h2p[(size_t)s2 * 32 + lane]);
        float2 v3 = __half22float2(h2p[(size_t)s3 * 32 + lane]);
        a0.x = fmaf(v0.x, n0, a0.x); a0.y = fmaf(v0.y, n0, a0.y);
        a1.x = fmaf(v1.x, n1, a1.x); a1.y = fmaf(v1.y, n1, a1.y);
        a2.x = fmaf(v2.x, n2, a2.x); a2.y = fmaf(v2.y, n2, a2.y);
        a3.x = fmaf(v3.x, n3, a3.x); a3.y = fmaf(v3.y, n3, a3.y);
    }
    for (; j < end; ++j) {
        int s0 = csrc[j];
        float n0 = dinv[s0];
        float2 v0 = __half22float2(h2p[(size_t)s0 * 32 + lane]);
        a0.x = fmaf(v0.x, n0, a0.x); a0.y = fmaf(v0.y, n0, a0.y);
    }
    float2 bv = reinterpret_cast<const float2*>(b)[lane];
    float2 r;
    r.x = fmaf(dd, (a0.x + a1.x) + (a2.x + a3.x), bv.x);
    r.y = fmaf(dd, (a0.y + a1.y) + (a2.y + a3.y), bv.y);
    reinterpret_cast<float2*>(out)[(size_t)node * 32 + lane] = r;
}

// -----------------------------------------------------------------------------
extern "C" void kernel_launch(void* const* d_in, const int* in_sizes, int n_in,
                              void* d_out, int out_size)
{
    const float* x  = (const float*)d_in[0];
    const int*   ei = (const int*)  d_in[1];
    const float* W1 = (const float*)d_in[2];
    const float* b1 = (const float*)d_in[3];
    const float* W2 = (const float*)d_in[4];
    const float* b2 = (const float*)d_in[5];
    float* out = (float*)d_out;

    const int hid1 = in_sizes[3];            // 128
    const int feat = in_sizes[2] / hid1;     // 128
    const int N    = in_sizes[0] / feat;     // 50000
    const int E    = in_sizes[1] / 2;        // 800000
    const int* src = ei;
    const int* dst = ei + E;

    void *p_h1, *p_a1, *p_h2, *p_deg, *p_dinv, *p_rs, *p_cur, *p_csrc, *p_bsum;
    cudaGetSymbolAddress(&p_h1,   g_h1);
    cudaGetSymbolAddress(&p_a1,   g_a1);
    cudaGetSymbolAddress(&p_h2,   g_h2);
    cudaGetSymbolAddress(&p_deg,  g_deg);
    cudaGetSymbolAddress(&p_dinv, g_dinv);
    cudaGetSymbolAddress(&p_rs,   g_rowstart);
    cudaGetSymbolAddress(&p_cur,  g_cursor);
    cudaGetSymbolAddress(&p_csrc, g_csrc);
    cudaGetSymbolAddress(&p_bsum, g_bsum);
    __half* h1  = (__half*)p_h1;
    float*  a1  = (float*) p_a1;
    __half* h2  = (__half*)p_h2;
    int*    deg = (int*)   p_deg;
    float*  dinv= (float*) p_dinv;
    int*    rs  = (int*)   p_rs;
    int*    cur = (int*)   p_cur;
    int*    csrc= (int*)   p_csrc;
    int*    bsum= (int*)   p_bsum;

    static cudaStream_t s_csr = nullptr;
    static cudaEvent_t  ev_root = nullptr, ev_csr = nullptr;
    if (s_csr == nullptr) {
        cudaFuncSetAttribute(hmma_gemm_kernel<HID1>,
                             cudaFuncAttributeMaxDynamicSharedMemorySize, HG_SMEM(HID1));
        cudaFuncSetAttribute(hmma_gemm_kernel<HID2>,
                             cudaFuncAttributeMaxDynamicSharedMemorySize, HG_SMEM(HID2));
        cudaStreamCreateWithFlags(&s_csr, cudaStreamNonBlocking);
        cudaEventCreateWithFlags(&ev_root, cudaEventDisableTiming);
        cudaEventCreateWithFlags(&ev_csr,  cudaEventDisableTiming);
    }

    const int T = 256;
    const int nscan = (N + SCAN_B - 1) / SCAN_B;    // 49 blocks
    const int gx    = (N + 127) / 128;
    const int gwarp = (N * 32 + T - 1) / T;
    const int e4    = (E + 3) / 4;                  // ILP-4 edge threads

    // ---- fork: CSR/degree chain on side stream, GEMM1 on main stream ----
    cudaEventRecord(ev_root, 0);
    cudaStreamWaitEvent(s_csr, ev_root, 0);

    cudaMemsetAsync(deg, 0, (size_t)N * sizeof(int), s_csr);
    count_deg_kernel  <<<(e4 + T - 1) / T, T, 0, s_csr>>>(dst, deg, E);
    scan_blocks_kernel<<<nscan, SCAN_B, 0, s_csr>>>(deg, rs, bsum, dinv, N);
    scan_add_kernel   <<<nscan, SCAN_B, 0, s_csr>>>(rs, cur, bsum, N, nscan, E);
    fill_csr_kernel   <<<(e4 + T - 1) / T, T, 0, s_csr>>>(src, dst, cur, csrc, E);
    cudaEventRecord(ev_csr, s_csr);

    // layer 1 GEMM (independent of degree chain): h1 = x @ W1 (fp16 out)
    hmma_gemm_kernel<HID1><<<gx, 256, HG_SMEM(HID1)>>>(x, W1, h1, N);

    // join: gathers need CSR + dinv
    cudaStreamWaitEvent(0, ev_csr, 0);

    // gather layer 1: a1 = relu(dinv_d * (dinv_d*h1[d] + sum dinv_s*h1[s]) + b1)
    gather128_kernel<<<gwarp, T>>>(h1, rs, csrc, dinv, b1, a1, N);

    // layer 2 GEMM: h2 = a1 @ W2 (fp16 out)
    hmma_gemm_kernel<HID2><<<gx, 256, HG_SMEM(HID2)>>>(a1, W2, h2, N);

    // gather layer 2 into out (no relu, fp32 out)
    gather64_kernel<<<gwarp, T>>>(h2, rs, csrc, dinv, b2, out, N);
}

// round 13
// speedup vs baseline: 1.2198x; 1.2035x over previous
#include <cuda_runtime.h>
#include <cuda_bf16.h>
#include <cuda_fp16.h>
#include <cstdint>

// Problem constants (GCL_GCN: N=50000, E=800000, FEAT=128, HID1=128, HID2=64)
#define N_MAX   50000
#define E_MAX   800000
#define HID1    128
#define HID2    64
#define SCAN_B  1024
#define SCAN_NBLOCKS ((N_MAX + SCAN_B - 1) / SCAN_B + 1)

// ---------------- scratch (static device globals; no allocation) -------------
__device__ __half g_h1 [(size_t)N_MAX * HID1];   // X @ W1 (fp16 payload)
__device__ __half g_a1 [(size_t)N_MAX * HID1];   // relu(aggregated layer1), fp16
__device__ __half g_h2 [(size_t)N_MAX * HID2];   // a1 @ W2 (fp16 payload)
__device__ int    g_deg [N_MAX];
__device__ float  g_dinv[N_MAX];
__device__ int    g_rowstart[N_MAX + 1];
__device__ int    g_cursor  [N_MAX];
__device__ int    g_csrc    [E_MAX];             // edges sorted by dst -> src ids
__device__ int    g_bsum    [SCAN_NBLOCKS + 1];  // per-block scan sums

// ---------------- helpers -----------------------------------------------------
__device__ __forceinline__ uint32_t h2_as_u32(__half2 h) {
    return *reinterpret_cast<uint32_t*>(&h);
}
__device__ __forceinline__ void mma_f16(
    float* c, const uint32_t* a, uint32_t b0, uint32_t b1)
{
    asm volatile(
        "mma.sync.aligned.m16n8k16.row.col.f32.f16.f16.f32 "
        "{%0,%1,%2,%3}, {%4,%5,%6,%7}, {%8,%9}, {%0,%1,%2,%3};"
        : "+f"(c[0]), "+f"(c[1]), "+f"(c[2]), "+f"(c[3])
        : "r"(a[0]), "r"(a[1]), "r"(a[2]), "r"(a[3]), "r"(b0), "r"(b1));
}
__device__ __forceinline__ float4 half4_to_float4(uint2 u) {
    float2 lo = __half22float2(*reinterpret_cast<__half2*>(&u.x));
    float2 hi = __half22float2(*reinterpret_cast<__half2*>(&u.y));
    return make_float4(lo.x, lo.y, hi.x, hi.y);
}

// ---------------- degree count (4 edges/thread for atomic MLP) -----------------
__global__ void count_deg_kernel(const int* __restrict__ dst, int* __restrict__ deg, int E) {
    int base = (blockIdx.x * blockDim.x + threadIdx.x) * 4;
    if (base + 3 < E) {
        int d0 = dst[base], d1 = dst[base + 1], d2 = dst[base + 2], d3 = dst[base + 3];
        atomicAdd(&deg[d0], 1);
        atomicAdd(&deg[d1], 1);
        atomicAdd(&deg[d2], 1);
        atomicAdd(&deg[d3], 1);
    } else {
        for (int e = base; e < E; ++e) atomicAdd(&deg[dst[e]], 1);
    }
}

// ---------------- scan phase A: per-block excl scan + dinv ---------------------
__global__ __launch_bounds__(SCAN_B) void scan_blocks_kernel(
    const int* __restrict__ deg, int* __restrict__ row_start,
    int* __restrict__ bsum, float* __restrict__ dinv, int N)
{
    __shared__ int warp_sums[32];
    const int lane = threadIdx.x & 31;
    const int wid  = threadIdx.x >> 5;
    int i = blockIdx.x * SCAN_B + threadIdx.x;
    int v = (i < N) ? deg[i] : 0;
    if (i < N) dinv[i] = rsqrtf((float)(v + 1));   // +1 self-loop
    int x = v;
    #pragma unroll
    for (int o = 1; o < 32; o <<= 1) {
        int t = __shfl_up_sync(0xffffffffu, x, o);
        if (lane >= o) x += t;
    }
    if (lane == 31) warp_sums[wid] = x;
    __syncthreads();
    if (wid == 0) {
        int ws = warp_sums[lane];
        #pragma unroll
        for (int o = 1; o < 32; o <<= 1) {
            int t = __shfl_up_sync(0xffffffffu, ws, o);
            if (lane >= o) ws += t;
        }
        warp_sums[lane] = ws;
    }
    __syncthreads();
    int excl = x - v + (wid > 0 ? warp_sums[wid - 1] : 0);
    if (i < N) row_start[i] = excl;
    if (threadIdx.x == SCAN_B - 1) bsum[blockIdx.x] = excl + v;
}

// ---------------- scan phase B: add block offsets (masked reduce per block) ----
__global__ __launch_bounds__(SCAN_B) void scan_add_kernel(
    int* __restrict__ row_start, int* __restrict__ cursor,
    const int* __restrict__ bsum, int N, int nscan, int E)
{
    __shared__ int s_off;
    if (threadIdx.x < 32) {
        int lane = threadIdx.x;
        int v = 0;
        if (lane < nscan && lane < blockIdx.x) v = bsum[lane];
        if (lane + 32 < nscan && lane + 32 < (int)blockIdx.x) v += bsum[lane + 32];
        #pragma unroll
        for (int o = 16; o; o >>= 1) v += __shfl_xor_sync(0xffffffffu, v, o);
        if (lane == 0) s_off = v;
    }
    __syncthreads();
    int i = blockIdx.x * SCAN_B + threadIdx.x;
    if (i < N) {
        int r = row_start[i] + s_off;
        row_start[i] = r;
        cursor[i]    = r;
    }
    if (i == 0) row_start[N] = E;    // total edge count is known
}

// ---------------- fill CSR (4 edges/thread for atomic MLP) ---------------------
__global__ void fill_csr_kernel(
    const int* __restrict__ src, const int* __restrict__ dst,
    int* __restrict__ cursor, int* __restrict__ csrc, int E)
{
    int base = (blockIdx.x * blockDim.x + threadIdx.x) * 4;
    if (base + 3 < E) {
        int d0 = dst[base],     d1 = dst[base + 1];
        int d2 = dst[base + 2], d3 = dst[base + 3];
        int s0 = src[base],     s1 = src[base + 1];
        int s2 = src[base + 2], s3 = src[base + 3];
        int p0 = atomicAdd(&cursor[d0], 1);
        int p1 = atomicAdd(&cursor[d1], 1);
        int p2 = atomicAdd(&cursor[d2], 1);
        int p3 = atomicAdd(&cursor[d3], 1);
        csrc[p0] = s0; csrc[p1] = s1; csrc[p2] = s2; csrc[p3] = s3;
    } else {
        for (int e = base; e < E; ++e) {
            int pos = atomicAdd(&cursor[dst[e]], 1);
            csrc[pos] = src[e];
        }
    }
}

// ---------------- fp16 HMMA GEMM: H(fp16) = X[N,128] @ W[128,COUT] -------------
// CTA: 256 thr (8 warps), tile 128 rows x COUT cols. Warp tile 32 x COUT/2.
// mma.sync m16n8k16 f16 inputs, f32 accum. A tile row-major halves (stride 136),
// W staged TRANSPOSED as Wt[n][k] halves (stride 136). Frag-load bank = 4g+t,
// conflict-free for both A and B.
// F16IN: X is fp16 (a1) vs fp32 (x).
#define HG2_SMEM(COUT) ((128 * 136 + (COUT) * 136) * 2)

template<int COUT, bool F16IN>
__global__ __launch_bounds__(256) void hmma_f16_gemm_kernel(
    const void* __restrict__ Xv, const float* __restrict__ W,
    __half* __restrict__ H, int N)
{
    constexpr int XS2 = 136;            // halves stride (272B, 16B aligned)
    constexpr int WS2 = 136;
    constexpr int NT  = COUT / 16;      // n-tiles per warp (warp cols = COUT/2)
    extern __shared__ __half smh[];
    __half* Xs = smh;                   // [128][XS2]
    __half* Ws = smh + 128 * XS2;       // [COUT][WS2]  (transposed: Ws[n][k])

    const int tid   = threadIdx.x;
    const int wid   = tid >> 5;
    const int lane  = tid & 31;
    const int g     = lane >> 2;
    const int t     = lane & 3;
    const int rbase = blockIdx.x * 128;

    // ---- stage X tile [128 r][128 k] -> fp16 ----
    if (F16IN) {
        const uint4* Xg = reinterpret_cast<const uint4*>(Xv);   // 8 halves each
        #pragma unroll
        for (int it = 0; it < 8; ++it) {                        // 2048 uint4
            int i  = tid + it * 256;
            int r  = i >> 4, q = i & 15;                        // 16 uint4 per row
            int gr = rbase + r;
            uint4 v = (gr < N) ? Xg[(size_t)gr * 16 + q]
                               : make_uint4(0u, 0u, 0u, 0u);
            *reinterpret_cast<uint4*>(&Xs[r * XS2 + q * 8]) = v;
        }
    } else {
        const float4* Xg4 = reinterpret_cast<const float4*>(Xv);
        #pragma unroll
        for (int it = 0; it < 16; ++it) {                       // 4096 float4
            int i  = tid + it * 256;
            int r  = i >> 5, k4 = i & 31;
            int gr = rbase + r;
            float4 v = (gr < N) ? Xg4[(size_t)gr * 32 + k4]
                                : make_float4(0.f, 0.f, 0.f, 0.f);
            uint2 u;
            u.x = h2_as_u32(__floats2half2_rn(v.x, v.y));
            u.y = h2_as_u32(__floats2half2_rn(v.z, v.w));
            *reinterpret_cast<uint2*>(&Xs[r * XS2 + k4 * 4]) = u;
        }
    }

    // ---- stage W transposed: Ws[n][2k2..2k2+1] = (W[2k2][n], W[2k2+1][n]) ----
    #pragma unroll
    for (int it = 0; it < (COUT * 64) / 256; ++it) {
        int i  = tid + it * 256;
        int n  = i % COUT, k2 = i / COUT;
        float w0 = W[(2 * k2)     * COUT + n];
        float w1 = W[(2 * k2 + 1) * COUT + n];
        *reinterpret_cast<__half2*>(&Ws[n * WS2 + 2 * k2]) = __floats2half2_rn(w0, w1);
    }
    __syncthreads();

    // ---- main loop: 8 k-steps of k=16 ----
    const int wr = (wid >> 1) * 32;             // warp row base
    const int wc = (wid & 1) * (COUT / 2);      // warp col base
    float c[2][NT][4];
    #pragma unroll
    for (int rb = 0; rb < 2; ++rb)
        #pragma unroll
        for (int nt = 0; nt < NT; ++nt)
            #pragma unroll
            for (int j = 0; j < 4; ++j) c[rb][nt][j] = 0.f;

    #pragma unroll
    for (int ks = 0; ks < 8; ++ks) {
        const int k0 = ks * 16;
        uint32_t a[2][4];
        #pragma unroll
        for (int rb = 0; rb < 2; ++rb) {
            const __half* xb = &Xs[(wr + rb * 16 + g) * XS2 + k0 + 2 * t];
            a[rb][0] = *reinterpret_cast<const uint32_t*>(xb);
            a[rb][1] = *reinterpret_cast<const uint32_t*>(xb + 8 * XS2);
            a[rb][2] = *reinterpret_cast<const uint32_t*>(xb + 8);
            a[rb][3] = *reinterpret_cast<const uint32_t*>(xb + 8 * XS2 + 8);
        }
        #pragma unroll
        for (int nt = 0; nt < NT; ++nt) {
            const __half* wb = &Ws[(wc + nt * 8 + g) * WS2 + k0 + 2 * t];
            uint32_t b0 = *reinterpret_cast<const uint32_t*>(wb);
            uint32_t b1 = *reinterpret_cast<const uint32_t*>(wb + 8);
            mma_f16(c[0][nt], a[0], b0, b1);
            mma_f16(c[1][nt], a[1], b0, b1);
        }
    }

    // ---- epilogue: fp16 stores (c layout: rows g/g+8, cols 2t,2t+1) ----
    #pragma unroll
    for (int rb = 0; rb < 2; ++rb) {
        int r0 = rbase + wr + rb * 16 + g;
        #pragma unroll
        for (int nt = 0; nt < NT; ++nt) {
            int col = wc + nt * 8 + 2 * t;
            if (r0 < N)
                *reinterpret_cast<__half2*>(&H[(size_t)r0 * COUT + col]) =
                    __floats2half2_rn(c[rb][nt][0], c[rb][nt][1]);
            if (r0 + 8 < N)
                *reinterpret_cast<__half2*>(&H[(size_t)(r0 + 8) * COUT + col]) =
                    __floats2half2_rn(c[rb][nt][2], c[rb][nt][3]);
        }
    }
}

// ---------------- CSR gather, 128 feats fp16 in / fp16 out (unroll-2) ----------
// sum = dinv_d * h[d] + sum_s dinv_s * h[s];  out = relu(dinv_d * sum + b)
__global__ __launch_bounds__(256) void gather128_kernel(
    const __half* __restrict__ hs, const int* __restrict__ rs,
    const int* __restrict__ csrc, const float* __restrict__ dinv,
    const float* __restrict__ b, __half* __restrict__ out, int N)
{
    int node = (blockIdx.x * blockDim.x + threadIdx.x) >> 5;
    int lane = threadIdx.x & 31;
    if (node >= N) return;
    int beg = rs[node], end = rs[node + 1];
    const uint2* h8 = reinterpret_cast<const uint2*>(hs);  // 4 halves per lane
    float dd = dinv[node];

    float4 sv = half4_to_float4(h8[(size_t)node * 32 + lane]);
    float4 a0 = make_float4(sv.x * dd, sv.y * dd, sv.z * dd, sv.w * dd);
    float4 a1 = make_float4(0.f, 0.f, 0.f, 0.f);
    int j = beg;
    for (; j + 1 < end; j += 2) {
        int s0 = csrc[j], s1 = csrc[j + 1];
        float n0 = dinv[s0], n1 = dinv[s1];
        float4 v0 = half4_to_float4(h8[(size_t)s0 * 32 + lane]);
        float4 v1 = half4_to_float4(h8[(size_t)s1 * 32 + lane]);
        a0.x = fmaf(v0.x, n0, a0.x); a0.y = fmaf(v0.y, n0, a0.y);
        a0.z = fmaf(v0.z, n0, a0.z); a0.w = fmaf(v0.w, n0, a0.w);
        a1.x = fmaf(v1.x, n1, a1.x); a1.y = fmaf(v1.y, n1, a1.y);
        a1.z = fmaf(v1.z, n1, a1.z); a1.w = fmaf(v1.w, n1, a1.w);
    }
    if (j < end) {
        int s0 = csrc[j];
        float n0 = dinv[s0];
        float4 v0 = half4_to_float4(h8[(size_t)s0 * 32 + lane]);
        a0.x = fmaf(v0.x, n0, a0.x); a0.y = fmaf(v0.y, n0, a0.y);
        a0.z = fmaf(v0.z, n0, a0.z); a0.w = fmaf(v0.w, n0, a0.w);
    }
    float4 bv = reinterpret_cast<const float4*>(b)[lane];
    float rx = fmaxf(fmaf(dd, a0.x + a1.x, bv.x), 0.f);
    float ry = fmaxf(fmaf(dd, a0.y + a1.y, bv.y), 0.f);
    float rz = fmaxf(fmaf(dd, a0.z + a1.z, bv.z), 0.f);
    float rw = fmaxf(fmaf(dd, a0.w + a1.w, bv.w), 0.f);
    uint2 o;
    o.x = h2_as_u32(__floats2half2_rn(rx, ry));
    o.y = h2_as_u32(__floats2half2_rn(rz, rw));
    reinterpret_cast<uint2*>(out)[(size_t)node * 32 + lane] = o;
}

// ---------------- CSR gather, 64 feats fp16 in / fp32 out (unroll-2) -----------
__global__ __launch_bounds__(256) void gather64_kernel(
    const __half* __restrict__ hs, const int* __restrict__ rs,
    const int* __restrict__ csrc, const float* __restrict__ dinv,
    const float* __restrict__ b, float* __restrict__ out, int N)
{
    int node = (blockIdx.x * blockDim.x + threadIdx.x) >> 5;
    int lane = threadIdx.x & 31;
    if (node >= N) return;
    int beg = rs[node], end = rs[node + 1];
    const __half2* h2p = reinterpret_cast<const __half2*>(hs);  // 2 halves per lane
    float dd = dinv[node];

    float2 sv = __half22float2(h2p[(size_t)node * 32 + lane]);
    float2 a0 = make_float2(sv.x * dd, sv.y * dd);
    float2 a1 = make_float2(0.f, 0.f);
    int j = beg;
    for (; j + 1 < end; j += 2) {
        int s0 = csrc[j], s1 = csrc[j + 1];
        float n0 = dinv[s0], n1 = dinv[s1];
        float2 v0 = __half22float2(h2p[(size_t)s0 * 32 + lane]);
        float2 v1 = __half22float2(h2p[(size_t)s1 * 32 + lane]);
        a0.x = fmaf(v0.x, n0, a0.x); a0.y = fmaf(v0.y, n0, a0.y);
        a1.x = fmaf(v1.x, n1, a1.x); a1.y = fmaf(v1.y, n1, a1.y);
    }
    if (j < end) {
        int s0 = csrc[j];
        float n0 = dinv[s0];
        float2 v0 = __half22float2(h2p[(size_t)s0 * 32 + lane]);
        a0.x = fmaf(v0.x, n0, a0.x); a0.y = fmaf(v0.y, n0, a0.y);
    }
    float2 bv = reinterpret_cast<const float2*>(b)[lane];
    float2 r;
    r.x = fmaf(dd, a0.x + a1.x, bv.x);
    r.y = fmaf(dd, a0.y + a1.y, bv.y);
    reinterpret_cast<float2*>(out)[(size_t)node * 32 + lane] = r;
}

// -----------------------------------------------------------------------------
extern "C" void kernel_launch(void* const* d_in, const int* in_sizes, int n_in,
                              void* d_out, int out_size)
{
    const float* x  = (const float*)d_in[0];
    const int*   ei = (const int*)  d_in[1];
    const float* W1 = (const float*)d_in[2];
    const float* b1 = (const float*)d_in[3];
    const float* W2 = (const float*)d_in[4];
    const float* b2 = (const float*)d_in[5];
    float* out = (float*)d_out;

    const int hid1 = in_sizes[3];            // 128
    const int feat = in_sizes[2] / hid1;     // 128
    const int N    = in_sizes[0] / feat;     // 50000
    const int E    = in_sizes[1] / 2;        // 800000
    const int* src = ei;
    const int* dst = ei + E;

    void *p_h1, *p_a1, *p_h2, *p_deg, *p_dinv, *p_rs, *p_cur, *p_csrc, *p_bsum;
    cudaGetSymbolAddress(&p_h1,   g_h1);
    cudaGetSymbolAddress(&p_a1,   g_a1);
    cudaGetSymbolAddress(&p_h2,   g_h2);
    cudaGetSymbolAddress(&p_deg,  g_deg);
    cudaGetSymbolAddress(&p_dinv, g_dinv);
    cudaGetSymbolAddress(&p_rs,   g_rowstart);
    cudaGetSymbolAddress(&p_cur,  g_cursor);
    cudaGetSymbolAddress(&p_csrc, g_csrc);
    cudaGetSymbolAddress(&p_bsum, g_bsum);
    __half* h1  = (__half*)p_h1;
    __half* a1  = (__half*)p_a1;
    __half* h2  = (__half*)p_h2;
    int*    deg = (int*)   p_deg;
    float*  dinv= (float*) p_dinv;
    int*    rs  = (int*)   p_rs;
    int*    cur = (int*)   p_cur;
    int*    csrc= (int*)   p_csrc;
    int*    bsum= (int*)   p_bsum;

    static cudaStream_t s_csr = nullptr;
    static cudaEvent_t  ev_root = nullptr, ev_csr = nullptr;
    if (s_csr == nullptr) {
        cudaFuncSetAttribute((const void*)hmma_f16_gemm_kernel<HID1, false>,
                             cudaFuncAttributeMaxDynamicSharedMemorySize, HG2_SMEM(HID1));
        cudaFuncSetAttribute((const void*)hmma_f16_gemm_kernel<HID2, true>,
                             cudaFuncAttributeMaxDynamicSharedMemorySize, HG2_SMEM(HID2));
        cudaStreamCreateWithFlags(&s_csr, cudaStreamNonBlocking);
        cudaEventCreateWithFlags(&ev_root, cudaEventDisableTiming);
        cudaEventCreateWithFlags(&ev_csr,  cudaEventDisableTiming);
    }

    const int T = 256;
    const int nscan = (N + SCAN_B - 1) / SCAN_B;    // 49 blocks
    const int gx    = (N + 127) / 128;
    const int gwarp = (N * 32 + T - 1) / T;
    const int e4    = (E + 3) / 4;                  // ILP-4 edge threads

    // ---- fork: CSR/degree chain on side stream, GEMM1 on main stream ----
    cudaEventRecord(ev_root, 0);
    cudaStreamWaitEvent(s_csr, ev_root, 0);

    cudaMemsetAsync(deg, 0, (size_t)N * sizeof(int), s_csr);
    count_deg_kernel  <<<(e4 + T - 1) / T, T, 0, s_csr>>>(dst, deg, E);
    scan_blocks_kernel<<<nscan, SCAN_B, 0, s_csr>>>(deg, rs, bsum, dinv, N);
    scan_add_kernel   <<<nscan, SCAN_B, 0, s_csr>>>(rs, cur, bsum, N, nscan, E);
    fill_csr_kernel   <<<(e4 + T - 1) / T, T, 0, s_csr>>>(src, dst, cur, csrc, E);
    cudaEventRecord(ev_csr, s_csr);

    // layer 1 GEMM (independent of degree chain): h1 = x @ W1 (fp16 out)
    hmma_f16_gemm_kernel<HID1, false><<<gx, 256, HG2_SMEM(HID1)>>>(x, W1, h1, N);

    // join: gathers need CSR + dinv
    cudaStreamWaitEvent(0, ev_csr, 0);

    // gather layer 1: a1 = relu(dinv_d * (dinv_d*h1[d] + sum dinv_s*h1[s]) + b1), fp16
    gather128_kernel<<<gwarp, T>>>(h1, rs, csrc, dinv, b1, a1, N);

    // layer 2 GEMM: h2 = a1 @ W2 (fp16 in, fp16 out)
    hmma_f16_gemm_kernel<HID2, true><<<gx, 256, HG2_SMEM(HID2)>>>(a1, W2, h2, N);

    // gather layer 2 into out (no relu, fp32 out)
    gather64_kernel<<<gwarp, T>>>(h2, rs, csrc, dinv, b2, out, N);
}